// round 1
// baseline (speedup 1.0000x reference)
#include <cuda_runtime.h>
#include <math.h>
#include <stdint.h>

#define BSZ 256
#define DIM 4096
#define TMAX 19
#define NTHREADS 256

// ---- scratch (no allocations allowed; __device__ globals) ----
__device__ float g_gradx[BSZ * DIM];
__device__ float g_grady[BSZ * DIM];
__device__ float g_yv[BSZ * DIM];
__device__ int   g_idxbuf[BSZ * TMAX];
__device__ float g_logfwd[BSZ];

// ======================= GEMM: C = A @ W + bias ========================
// A: [256 x 4096] row-major, W: [4096 x 4096] row-major, C: [256 x 4096]
// mode==0: A = Aext (x), C = g_gradx ; mode==1: A = g_yv, C = g_grady
#define BM 64
#define BN 64
#define BKK 16
#define ASTR 68   // padded stride (68*4B = 272B = 17*16B -> float4 aligned, fewer bank conflicts)

__global__ __launch_bounds__(256) void gemm_kernel(
    const float* __restrict__ Aext, const float* __restrict__ W,
    const float* __restrict__ bias, int mode)
{
    const float* A = mode ? (const float*)g_yv : Aext;
    float*       C = mode ? g_grady : g_gradx;

    __shared__ __align__(16) float As[BKK][ASTR]; // transposed A tile: As[k][m]
    __shared__ __align__(16) float Bs[BKK][BN];

    int tid = threadIdx.x;
    int bm = blockIdx.y * BM;
    int bn = blockIdx.x * BN;

    int arow = tid >> 2;            // 0..63
    int acol = (tid & 3) << 2;      // 0,4,8,12
    int brow = tid >> 4;            // 0..15
    int bcol = (tid & 15) << 2;     // 0..60
    int tx = tid & 15, ty = tid >> 4;

    const float* Ap = A + (size_t)(bm + arow) * DIM + acol;
    const float* Wp = W + (size_t)brow * DIM + bn + bcol;

    float4 av = *(const float4*)Ap;
    float4 wv = *(const float4*)Wp;

    float acc[4][4];
    #pragma unroll
    for (int i = 0; i < 4; i++)
        #pragma unroll
        for (int j = 0; j < 4; j++) acc[i][j] = 0.f;

    for (int k0 = 0; k0 < DIM; k0 += BKK) {
        __syncthreads();
        As[acol + 0][arow] = av.x;
        As[acol + 1][arow] = av.y;
        As[acol + 2][arow] = av.z;
        As[acol + 3][arow] = av.w;
        *(float4*)&Bs[brow][bcol] = wv;
        __syncthreads();
        if (k0 + BKK < DIM) {   // software prefetch next tiles (hides GMEM latency)
            av = *(const float4*)(Ap + k0 + BKK);
            wv = *(const float4*)(Wp + (size_t)(k0 + BKK) * DIM);
        }
        #pragma unroll
        for (int k = 0; k < BKK; k++) {
            float4 a4 = *(const float4*)&As[k][ty << 2];
            float4 b4 = *(const float4*)&Bs[k][tx << 2];
            float ar[4] = {a4.x, a4.y, a4.z, a4.w};
            float br[4] = {b4.x, b4.y, b4.z, b4.w};
            #pragma unroll
            for (int i = 0; i < 4; i++)
                #pragma unroll
                for (int j = 0; j < 4; j++)
                    acc[i][j] += ar[i] * br[j];
        }
    }

    float4 bb = *(const float4*)&bias[bn + (tx << 2)];
    #pragma unroll
    for (int i = 0; i < 4; i++) {
        int row = bm + (ty << 2) + i;
        float4 o;
        o.x = acc[i][0] + bb.x;
        o.y = acc[i][1] + bb.y;
        o.z = acc[i][2] + bb.z;
        o.w = acc[i][3] + bb.w;
        *(float4*)&C[(size_t)row * DIM + bn + (tx << 2)] = o;
    }
}

// ================ Gumbel: -log(-log u), fast-math-safe =================
// If compiled with fast-math, __logf has 2^-21 ABSOLUTE error which destroys
// relative accuracy of -log(u) for u near 1 (exactly the top-Gumbel winners).
// log1pf(u-1) keeps relative accuracy there (u-1 exact by Sterbenz).
__device__ __forceinline__ float gumbel_from_u(float u) {
    float nl = (u > 0.75f) ? (-log1pf(u - 1.0f)) : (-logf(u));
    return -logf(nl);
}

// ============================ forward scan =============================
// One CTA per batch row. Maintains l_j = delta_j * 0.5 * grad_x_j in smem,
// incremental logsumexp S, Gumbel-argmax per active step, records flip idx,
// accumulates log_fwd = sum(sel_f) + score_x.
__global__ __launch_bounds__(256) void scan_kernel(
    const float* __restrict__ x, const float* __restrict__ unif,
    const int* __restrict__ radius, const float* __restrict__ bias)
{
    __shared__ __align__(16) float al[DIM];  // current l_j
    __shared__ __align__(16) float yb[DIM];  // current bits (0/1)
    __shared__ float rf[8];
    __shared__ int   ri[8];
    __shared__ float rsum[8], rsum2[8];

    int b = blockIdx.x;
    int tid = threadIdx.x;
    int lane = tid & 31, wid = tid >> 5;

    const float* gx = g_gradx + (size_t)b * DIM;
    const float* xr = x + (size_t)b * DIM;

    float s_part = 0.f, sc_part = 0.f;
    for (int j = tid; j < DIM; j += NTHREADS) {
        float g  = gx[j];
        float xv = xr[j];
        float l  = (1.f - 2.f * xv) * (0.5f * g);
        al[j] = l;
        yb[j] = xv;
        s_part  += expf(l);                    // S0 = sum exp(l_j)
        sc_part += xv * 0.5f * (g + bias[j]);  // score_x = 0.5 x.grad + 0.5 x.b
    }
    #pragma unroll
    for (int o = 16; o; o >>= 1) {
        s_part  += __shfl_down_sync(0xffffffffu, s_part, o);
        sc_part += __shfl_down_sync(0xffffffffu, sc_part, o);
    }
    if (lane == 0) { rsum[wid] = s_part; rsum2[wid] = sc_part; }
    __syncthreads();

    float S = 0.f, score = 0.f;
    if (tid == 0) {
        #pragma unroll
        for (int w = 0; w < 8; w++) { S += rsum[w]; score += rsum2[w]; }
    }

    int r = radius[b];
    float sum_sel = 0.f;

    for (int t = 0; t < r; t++) {
        __syncthreads();  // al/yb updates from previous step visible
        const float* up = unif + ((size_t)t * BSZ + b) * DIM;

        float best = -3.0e38f; int bi = 0;
        #pragma unroll
        for (int it = 0; it < DIM / (NTHREADS * 4); it++) {  // 4 sweeps
            int j = (tid << 2) + (it << 10);
            float4 u4 = *(const float4*)(up + j);
            float4 a4 = *(const float4*)&al[j];
            float k0 = a4.x + gumbel_from_u(u4.x);
            float k1 = a4.y + gumbel_from_u(u4.y);
            float k2 = a4.z + gumbel_from_u(u4.z);
            float k3 = a4.w + gumbel_from_u(u4.w);
            if (k0 > best) { best = k0; bi = j; }
            if (k1 > best) { best = k1; bi = j + 1; }
            if (k2 > best) { best = k2; bi = j + 2; }
            if (k3 > best) { best = k3; bi = j + 3; }
        }
        // warp argmax (tie -> lower index, matching jnp.argmax first-max)
        #pragma unroll
        for (int o = 16; o; o >>= 1) {
            float ov = __shfl_down_sync(0xffffffffu, best, o);
            int   oi = __shfl_down_sync(0xffffffffu, bi, o);
            if (ov > best || (ov == best && oi < bi)) { best = ov; bi = oi; }
        }
        if (lane == 0) { rf[wid] = best; ri[wid] = bi; }
        __syncthreads();
        if (tid == 0) {
            float bv = rf[0]; int bbi = ri[0];
            #pragma unroll
            for (int w = 1; w < 8; w++)
                if (rf[w] > bv || (rf[w] == bv && ri[w] < bbi)) { bv = rf[w]; bbi = ri[w]; }
            float l = al[bbi];                 // pre-flip l at chosen idx
            sum_sel += l - logf(S);            // sel_f[t] = l - logsumexp
            S += expf(-l) - expf(l);           // incremental logsumexp update
            al[bbi] = -l;                      // flip bit -> l negates
            yb[bbi] = 1.0f - yb[bbi];
            g_idxbuf[b * TMAX + t] = bbi;
        }
    }
    __syncthreads();
    for (int j = tid; j < DIM; j += NTHREADS)
        g_yv[(size_t)b * DIM + j] = yb[j];
    if (tid == 0) g_logfwd[b] = sum_sel + score;
}

// ==================== backward pass + accept + output ===================
__global__ __launch_bounds__(256) void bwd_kernel(
    const float* __restrict__ x, const float* __restrict__ bias,
    const float* __restrict__ uacc, const int* __restrict__ radius,
    float* __restrict__ out)
{
    __shared__ __align__(16) float bl[DIM];  // l_j over current (reverting) delta, with grad_y
    __shared__ float rsum[8], rsum2[8];
    __shared__ float s_acc;

    int b = blockIdx.x;
    int tid = threadIdx.x;
    int lane = tid & 31, wid = tid >> 5;

    const float* gy = g_grady + (size_t)b * DIM;
    const float* yr = g_yv + (size_t)b * DIM;

    float s_part = 0.f, sc_part = 0.f;
    for (int j = tid; j < DIM; j += NTHREADS) {
        float g  = gy[j];
        float yv = yr[j];
        float l  = (1.f - 2.f * yv) * (0.5f * g);
        bl[j] = l;
        s_part  += expf(l);                    // Sy over delta_y
        sc_part += yv * 0.5f * (g + bias[j]);  // score_y
    }
    #pragma unroll
    for (int o = 16; o; o >>= 1) {
        s_part  += __shfl_down_sync(0xffffffffu, s_part, o);
        sc_part += __shfl_down_sync(0xffffffffu, sc_part, o);
    }
    if (lane == 0) { rsum[wid] = s_part; rsum2[wid] = sc_part; }
    __syncthreads();  // also makes bl[] visible to thread 0

    if (tid == 0) {
        float S = 0.f, score = 0.f;
        #pragma unroll
        for (int w = 0; w < 8; w++) { S += rsum[w]; score += rsum2[w]; }
        int r = radius[b];
        float sum_sel = 0.f;
        // iterate t = r-1 .. 0 ; entering iteration t, S and bl are over delta_{t+1}
        for (int t = r - 1; t >= 0; t--) {
            int i = g_idxbuf[b * TMAX + t];
            float l = bl[i];                   // delta_{t+1}[i] * gy[i] * 0.5
            sum_sel += l - logf(S);            // sel_b[t]
            S += expf(-l) - expf(l);           // revert flip t -> delta_t
            bl[i] = -l;
        }
        float log_bwd = sum_sel + score;
        float ratio = expf(log_bwd - g_logfwd[b]);
        s_acc = (ratio >= uacc[b]) ? 1.0f : 0.0f;
    }
    __syncthreads();

    float a = s_acc;
    const float* xr = x + (size_t)b * DIM;
    float* orow = out + (size_t)b * DIM;
    for (int j = tid << 2; j < DIM; j += NTHREADS * 4) {
        float4 yv4 = *(const float4*)(yr + j);
        float4 xv4 = *(const float4*)(xr + j);
        float4 o;
        o.x = (a != 0.f) ? yv4.x : xv4.x;
        o.y = (a != 0.f) ? yv4.y : xv4.y;
        o.z = (a != 0.f) ? yv4.z : xv4.z;
        o.w = (a != 0.f) ? yv4.w : xv4.w;
        *(float4*)(orow + j) = o;
    }
}

// =============================== launch ================================
extern "C" void kernel_launch(void* const* d_in, const int* in_sizes, int n_in,
                              void* d_out, int out_size)
{
    const float* x      = (const float*)d_in[0];
    const float* W      = (const float*)d_in[1];
    const float* bias   = (const float*)d_in[2];
    const float* unif   = (const float*)d_in[3];
    const float* uacc   = (const float*)d_in[4];
    const int*   radius = (const int*)d_in[5];
    float* out = (float*)d_out;

    dim3 ggrid(DIM / BN, BSZ / BM);  // (64, 4)

    gemm_kernel<<<ggrid, 256>>>(x, W, bias, 0);                 // grad_x
    scan_kernel<<<BSZ, 256>>>(x, unif, radius, bias);           // scan -> y, idx, log_fwd
    gemm_kernel<<<ggrid, 256>>>(x /*unused*/, W, bias, 1);      // grad_y
    bwd_kernel<<<BSZ, 256>>>(x, bias, uacc, radius, out);       // accept + output
}

// round 5
// speedup vs baseline: 2.0500x; 2.0500x over previous
#include <cuda_runtime.h>
#include <cuda_bf16.h>
#include <math.h>
#include <stdint.h>

#define BSZ 256
#define DIM 4096
#define TMAX 19
#define NTHREADS 256

// ------------- scratch (__device__ globals; aligned, no allocations) -------------
__device__ __align__(128) __nv_bfloat16 g_wsplit[3ull * DIM * DIM]; // 96MB: W = w1+w2+w3 exactly
__device__ __align__(128) __nv_bfloat16 g_abf16[BSZ * DIM];         // x as bf16 (exact, binary)
__device__ __align__(128) float g_gradx[BSZ * DIM];
__device__ __align__(128) float g_yv[BSZ * DIM];
__device__ __align__(128) int   g_idxbuf[BSZ * TMAX];
__device__ __align__(128) float g_logfwd[BSZ];

// ======================= helpers =======================
__device__ __forceinline__ uint32_t smem_u32(const void* p) {
    uint32_t a;
    asm("{ .reg .u64 t; cvta.to.shared.u64 t, %1; cvt.u32.u64 %0, t; }" : "=r"(a) : "l"(p));
    return a;
}
__device__ __forceinline__ void cpasync16(uint32_t dst, const void* src) {
    asm volatile("cp.async.cg.shared.global [%0], [%1], 16;" :: "r"(dst), "l"(src) : "memory");
}
#define CP_COMMIT() asm volatile("cp.async.commit_group;" ::: "memory")
#define CP_WAIT2()  asm volatile("cp.async.wait_group 2;" ::: "memory")

__device__ __forceinline__ void ldsm_x4(uint32_t& r0, uint32_t& r1, uint32_t& r2, uint32_t& r3,
                                        uint32_t addr) {
    asm volatile("ldmatrix.sync.aligned.m8n8.x4.shared.b16 {%0,%1,%2,%3}, [%4];"
                 : "=r"(r0), "=r"(r1), "=r"(r2), "=r"(r3) : "r"(addr));
}
__device__ __forceinline__ void mma16816(float& c0, float& c1, float& c2, float& c3,
                                         uint32_t a0, uint32_t a1, uint32_t a2, uint32_t a3,
                                         uint32_t b0, uint32_t b1) {
    asm volatile("mma.sync.aligned.m16n8k16.row.col.f32.bf16.bf16.f32 "
                 "{%0,%1,%2,%3}, {%4,%5,%6,%7}, {%8,%9}, {%0,%1,%2,%3};"
                 : "+f"(c0), "+f"(c1), "+f"(c2), "+f"(c3)
                 : "r"(a0), "r"(a1), "r"(a2), "r"(a3), "r"(b0), "r"(b1));
}

// ====================== split W into 3 exact bf16 terms ======================
__global__ __launch_bounds__(256) void split_w_kernel(const float* __restrict__ W) {
    size_t i4 = ((size_t)blockIdx.x * 256 + threadIdx.x);
    float4 w = ((const float4*)W)[i4];
    float v[4] = {w.x, w.y, w.z, w.w};
    size_t base = i4 * 4;
    #pragma unroll
    for (int s = 0; s < 3; s++) {
        __nv_bfloat16 h0 = __float2bfloat16_rn(v[0]); v[0] -= __bfloat162float(h0);
        __nv_bfloat16 h1 = __float2bfloat16_rn(v[1]); v[1] -= __bfloat162float(h1);
        __nv_bfloat16 h2 = __float2bfloat16_rn(v[2]); v[2] -= __bfloat162float(h2);
        __nv_bfloat16 h3 = __float2bfloat16_rn(v[3]); v[3] -= __bfloat162float(h3);
        __nv_bfloat162* d2 = (__nv_bfloat162*)(g_wsplit + (size_t)s * DIM * DIM + base);
        d2[0] = __nv_bfloat162(h0, h1);
        d2[1] = __nv_bfloat162(h2, h3);
    }
}

__global__ __launch_bounds__(256) void conv_x_kernel(const float* __restrict__ x) {
    size_t i4 = ((size_t)blockIdx.x * 256 + threadIdx.x);
    float4 w = ((const float4*)x)[i4];
    __nv_bfloat162* d2 = (__nv_bfloat162*)(g_abf16 + i4 * 4);
    d2[0] = __nv_bfloat162(__float2bfloat16_rn(w.x), __float2bfloat16_rn(w.y));
    d2[1] = __nv_bfloat162(__float2bfloat16_rn(w.z), __float2bfloat16_rn(w.w));
}

// ============== GEMM via mma.sync (HMMA): gradx = x@W + b ==============
// C[256,4096] = sum_s A[256,4096]_bf16 @ Ws^T  (W symmetric; B rows = W rows, K-contig)
#define BM 64
#define BN 128
#define BKE 64                 // K elements per stage (128 bytes/row)
#define NSTAGE 4
#define NIT (3 * DIM / BKE)    // 192
#define STAGE_BYTES (BM * 128 + BN * 128)      // 8KB A + 16KB B = 24576
#define SMEM_TOTAL (NSTAGE * STAGE_BYTES)      // 98304

// stage buf layout: [A: BM rows x 128B][B: BN rows x 128B], both row-swizzled
__device__ __forceinline__ void load_stage(uint32_t sbase, int it, int buf, int bm, int bn, int tid) {
    int kk0 = it * BKE;
    int sp = kk0 >> 12;                 // which split (0..2)
    int ki = kk0 & (DIM - 1);           // k offset within split
    const __nv_bfloat16* Ab = g_abf16 + (size_t)bm * DIM + ki;
    const __nv_bfloat16* Bb = g_wsplit + (size_t)sp * DIM * DIM + (size_t)bn * DIM + ki;
    uint32_t abuf = sbase + buf * STAGE_BYTES;
    uint32_t bbuf = abuf + BM * 128;
    // A: 64 rows x 8 chunks = 512 chunks; 2 per thread
    #pragma unroll
    for (int i = 0; i < 2; i++) {
        int c = tid + i * 256;
        int row = c >> 3, ch = c & 7;
        uint32_t off = row * 128 + ((ch * 16) ^ ((row & 7) * 16));
        cpasync16(abuf + off, Ab + (size_t)row * DIM + ch * 8);
    }
    // B: 128 rows x 8 chunks = 1024 chunks; 4 per thread
    #pragma unroll
    for (int i = 0; i < 4; i++) {
        int c = tid + i * 256;
        int row = c >> 3, ch = c & 7;
        uint32_t off = row * 128 + ((ch * 16) ^ ((row & 7) * 16));
        cpasync16(bbuf + off, Bb + (size_t)row * DIM + ch * 8);
    }
    CP_COMMIT();
}

__global__ __launch_bounds__(256) void gemm_mma(const float* __restrict__ bias) {
    extern __shared__ __align__(128) char dsm[];
    uint32_t sbase = smem_u32(dsm);
    int tid = threadIdx.x;
    int wid = tid >> 5, lane = tid & 31;
    int bn = blockIdx.x * BN;
    int bm = blockIdx.y * BM;

    int wm = (wid >> 2) * 32;           // warp m offset (0,32)
    int wn = (wid & 3) * 32;            // warp n offset (0..96)

    // ldmatrix lane addressing (precomputed row components)
    int tile = lane >> 3, rl = lane & 7;
    // A frag x4: tiles = (rows0-7,k0),(rows8-15,k0),(rows0-7,k16B),(rows8-15,k16B)
    int a_row_off = (tile & 1) * 8 + rl;
    int a_kh = (tile >> 1) * 16;        // byte offset in k
    // B frag x4: tiles = (n0-7,k0),(n0-7,k16B),(n8-15,k0),(n8-15,k16B)
    int b_n_off = (tile >> 1) * 8 + rl;
    int b_kh = (tile & 1) * 16;

    int arow0 = wm + a_row_off;         // fi=0
    int arow1 = arow0 + 16;             // fi=1
    uint32_t a_base0 = arow0 * 128, a_rm0 = (arow0 & 7) * 16;
    uint32_t a_base1 = arow1 * 128, a_rm1 = (arow1 & 7) * 16;
    int bnr0 = wn + b_n_off;            // n group 0 (n 0-15)
    int bnr1 = bnr0 + 16;               // n group 1 (n 16-31)
    uint32_t b_base0 = bnr0 * 128, b_rm0 = (bnr0 & 7) * 16;
    uint32_t b_base1 = bnr1 * 128, b_rm1 = (bnr1 & 7) * 16;

    float c[2][4][4];
    #pragma unroll
    for (int i = 0; i < 2; i++)
        #pragma unroll
        for (int j = 0; j < 4; j++)
            #pragma unroll
            for (int k = 0; k < 4; k++) c[i][j][k] = 0.f;

    load_stage(sbase, 0, 0, bm, bn, tid);
    load_stage(sbase, 1, 1, bm, bn, tid);
    load_stage(sbase, 2, 2, bm, bn, tid);

    for (int it = 0; it < NIT; ++it) {
        CP_WAIT2();
        __syncthreads();
        int buf = it & 3;
        uint32_t Asm = sbase + buf * STAGE_BYTES;
        uint32_t Bsm = Asm + BM * 128;
        #pragma unroll
        for (int ks = 0; ks < 4; ks++) {
            uint32_t kb = ks * 32;
            uint32_t a0[4], a1[4], b0[4], b1[4];
            ldsm_x4(a0[0], a0[1], a0[2], a0[3], Asm + a_base0 + ((kb + a_kh) ^ a_rm0));
            ldsm_x4(a1[0], a1[1], a1[2], a1[3], Asm + a_base1 + ((kb + a_kh) ^ a_rm1));
            ldsm_x4(b0[0], b0[1], b0[2], b0[3], Bsm + b_base0 + ((kb + b_kh) ^ b_rm0));
            ldsm_x4(b1[0], b1[1], b1[2], b1[3], Bsm + b_base1 + ((kb + b_kh) ^ b_rm1));
            // n-frags: bj0: b0[0],b0[1] ; bj1: b0[2],b0[3] ; bj2: b1[0],b1[1] ; bj3: b1[2],b1[3]
            #pragma unroll
            for (int fi = 0; fi < 2; fi++) {
                uint32_t* a = fi ? a1 : a0;
                mma16816(c[fi][0][0], c[fi][0][1], c[fi][0][2], c[fi][0][3],
                         a[0], a[1], a[2], a[3], b0[0], b0[1]);
                mma16816(c[fi][1][0], c[fi][1][1], c[fi][1][2], c[fi][1][3],
                         a[0], a[1], a[2], a[3], b0[2], b0[3]);
                mma16816(c[fi][2][0], c[fi][2][1], c[fi][2][2], c[fi][2][3],
                         a[0], a[1], a[2], a[3], b1[0], b1[1]);
                mma16816(c[fi][3][0], c[fi][3][1], c[fi][3][2], c[fi][3][3],
                         a[0], a[1], a[2], a[3], b1[2], b1[3]);
            }
        }
        __syncthreads();
        if (it + 3 < NIT) load_stage(sbase, it + 3, (it + 3) & 3, bm, bn, tid);
    }

    // epilogue: c[fi][bj]: {c0,c1}@(row=wm+fi*16+lane/4, col=wn+bj*8+2*(lane%4))
    //                      {c2,c3}@(row+8, same col)
    int rbase = bm + wm + (lane >> 2);
    int cbase = bn + wn + 2 * (lane & 3);
    #pragma unroll
    for (int fi = 0; fi < 2; fi++) {
        #pragma unroll
        for (int bj = 0; bj < 4; bj++) {
            int col = cbase + bj * 8;
            float bx = bias[col], by = bias[col + 1];
            int r0 = rbase + fi * 16;
            float2 v0 = {c[fi][bj][0] + bx, c[fi][bj][1] + by};
            float2 v1 = {c[fi][bj][2] + bx, c[fi][bj][3] + by};
            *(float2*)&g_gradx[(size_t)r0 * DIM + col] = v0;
            *(float2*)&g_gradx[(size_t)(r0 + 8) * DIM + col] = v1;
        }
    }
}

// ================ Gumbel: -log(-log u), fast-math-safe =================
__device__ __forceinline__ float gumbel_from_u(float u) {
    float nl = (u > 0.75f) ? (-log1pf(u - 1.0f)) : (-logf(u));
    return -logf(nl);
}

// ============================ forward scan =============================
__global__ __launch_bounds__(256) void scan_kernel(
    const float* __restrict__ x, const float* __restrict__ unif,
    const int* __restrict__ radius, const float* __restrict__ bias)
{
    __shared__ __align__(16) float al[DIM];
    __shared__ __align__(16) float yb[DIM];
    __shared__ float rf[8];
    __shared__ int   ri[8];
    __shared__ float rsum[8], rsum2[8];

    int b = blockIdx.x;
    int tid = threadIdx.x;
    int lane = tid & 31, wid = tid >> 5;

    const float* gx = g_gradx + (size_t)b * DIM;
    const float* xr = x + (size_t)b * DIM;

    float s_part = 0.f, sc_part = 0.f;
    for (int j = tid; j < DIM; j += NTHREADS) {
        float g  = gx[j];
        float xv = xr[j];
        float l  = (1.f - 2.f * xv) * (0.5f * g);
        al[j] = l;
        yb[j] = xv;
        s_part  += expf(l);
        sc_part += xv * 0.5f * (g + bias[j]);
    }
    #pragma unroll
    for (int o = 16; o; o >>= 1) {
        s_part  += __shfl_down_sync(0xffffffffu, s_part, o);
        sc_part += __shfl_down_sync(0xffffffffu, sc_part, o);
    }
    if (lane == 0) { rsum[wid] = s_part; rsum2[wid] = sc_part; }
    __syncthreads();

    float S = 0.f, score = 0.f;
    if (tid == 0) {
        #pragma unroll
        for (int w = 0; w < 8; w++) { S += rsum[w]; score += rsum2[w]; }
    }

    int r = radius[b];
    float sum_sel = 0.f;

    for (int t = 0; t < r; t++) {
        __syncthreads();
        const float* up = unif + ((size_t)t * BSZ + b) * DIM;

        float best = -3.0e38f; int bi = 0;
        #pragma unroll
        for (int it = 0; it < DIM / (NTHREADS * 4); it++) {
            int j = (tid << 2) + (it << 10);
            float4 u4 = *(const float4*)(up + j);
            float4 a4 = *(const float4*)&al[j];
            float k0 = a4.x + gumbel_from_u(u4.x);
            float k1 = a4.y + gumbel_from_u(u4.y);
            float k2 = a4.z + gumbel_from_u(u4.z);
            float k3 = a4.w + gumbel_from_u(u4.w);
            if (k0 > best) { best = k0; bi = j; }
            if (k1 > best) { best = k1; bi = j + 1; }
            if (k2 > best) { best = k2; bi = j + 2; }
            if (k3 > best) { best = k3; bi = j + 3; }
        }
        #pragma unroll
        for (int o = 16; o; o >>= 1) {
            float ov = __shfl_down_sync(0xffffffffu, best, o);
            int   oi = __shfl_down_sync(0xffffffffu, bi, o);
            if (ov > best || (ov == best && oi < bi)) { best = ov; bi = oi; }
        }
        if (lane == 0) { rf[wid] = best; ri[wid] = bi; }
        __syncthreads();
        if (tid == 0) {
            float bv = rf[0]; int bbi = ri[0];
            #pragma unroll
            for (int w = 1; w < 8; w++)
                if (rf[w] > bv || (rf[w] == bv && ri[w] < bbi)) { bv = rf[w]; bbi = ri[w]; }
            float l = al[bbi];
            sum_sel += l - logf(S);
            S += expf(-l) - expf(l);
            al[bbi] = -l;
            yb[bbi] = 1.0f - yb[bbi];
            g_idxbuf[b * TMAX + t] = bbi;
        }
    }
    __syncthreads();
    for (int j = tid; j < DIM; j += NTHREADS)
        g_yv[(size_t)b * DIM + j] = yb[j];
    if (tid == 0) g_logfwd[b] = sum_sel + score;
}

// ============ fused: sparse grad_y + backward + accept + output ============
// grad_y = grad_x + sum_j (y_j - x_j) * W[j,:]   (rank <= 19, W symmetric)
__global__ __launch_bounds__(256) void bwd_fused(
    const float* __restrict__ x, const float* __restrict__ W,
    const float* __restrict__ bias, const float* __restrict__ uacc,
    const int* __restrict__ radius, float* __restrict__ out)
{
    __shared__ __align__(16) float gy[DIM];
    __shared__ float rsum[8], rsum2[8];
    __shared__ int   fidx[32];
    __shared__ float fsgn[32];
    __shared__ int   nf;
    __shared__ float s_acc;

    int b = blockIdx.x;
    int tid = threadIdx.x;
    int lane = tid & 31, wid = tid >> 5;

    const float* yr  = g_yv + (size_t)b * DIM;
    const float* xr  = x + (size_t)b * DIM;
    const float* gxr = g_gradx + (size_t)b * DIM;

    if (tid == 0) nf = 0;
    __syncthreads();

    for (int j = tid; j < DIM; j += NTHREADS) {
        float yv = yr[j], xv = xr[j];
        gy[j] = gxr[j];
        if (yv != xv) {
            int p = atomicAdd(&nf, 1);
            fidx[p] = j; fsgn[p] = yv - xv;
        }
    }
    __syncthreads();
    if (tid == 0 && nf > 1) {       // sort -> deterministic accumulation order
        for (int a = 0; a < nf - 1; a++)
            for (int cc = 0; cc < nf - 1 - a; cc++)
                if (fidx[cc] > fidx[cc + 1]) {
                    int ti = fidx[cc]; fidx[cc] = fidx[cc + 1]; fidx[cc + 1] = ti;
                    float ts = fsgn[cc]; fsgn[cc] = fsgn[cc + 1]; fsgn[cc + 1] = ts;
                }
    }
    __syncthreads();
    int n = nf;
    for (int j = tid; j < DIM; j += NTHREADS) {
        float acc = gy[j];
        for (int f = 0; f < n; f++)
            acc += fsgn[f] * W[(size_t)fidx[f] * DIM + j];
        gy[j] = acc;
    }
    __syncthreads();

    float s_part = 0.f, sc_part = 0.f;
    for (int j = tid; j < DIM; j += NTHREADS) {
        float g  = gy[j];
        float yv = yr[j];
        float l  = (1.f - 2.f * yv) * (0.5f * g);
        s_part  += expf(l);
        sc_part += yv * 0.5f * (g + bias[j]);
        gy[j] = l;
    }
    #pragma unroll
    for (int o = 16; o; o >>= 1) {
        s_part  += __shfl_down_sync(0xffffffffu, s_part, o);
        sc_part += __shfl_down_sync(0xffffffffu, sc_part, o);
    }
    if (lane == 0) { rsum[wid] = s_part; rsum2[wid] = sc_part; }
    __syncthreads();

    if (tid == 0) {
        float S = 0.f, score = 0.f;
        #pragma unroll
        for (int w = 0; w < 8; w++) { S += rsum[w]; score += rsum2[w]; }
        int r = radius[b];
        float sum_sel = 0.f;
        for (int t = r - 1; t >= 0; t--) {
            int i = g_idxbuf[b * TMAX + t];
            float l = gy[i];
            sum_sel += l - logf(S);
            S += expf(-l) - expf(l);
            gy[i] = -l;
        }
        float log_bwd = sum_sel + score;
        float ratio = expf(log_bwd - g_logfwd[b]);
        s_acc = (ratio >= uacc[b]) ? 1.0f : 0.0f;
    }
    __syncthreads();

    float a = s_acc;
    float* orow = out + (size_t)b * DIM;
    for (int j = tid << 2; j < DIM; j += NTHREADS * 4) {
        float4 yv4 = *(const float4*)(yr + j);
        float4 xv4 = *(const float4*)(xr + j);
        float4 o;
        o.x = (a != 0.f) ? yv4.x : xv4.x;
        o.y = (a != 0.f) ? yv4.y : xv4.y;
        o.z = (a != 0.f) ? yv4.z : xv4.z;
        o.w = (a != 0.f) ? yv4.w : xv4.w;
        *(float4*)(orow + j) = o;
    }
}

// =============================== launch ================================
extern "C" void kernel_launch(void* const* d_in, const int* in_sizes, int n_in,
                              void* d_out, int out_size)
{
    const float* x      = (const float*)d_in[0];
    const float* W      = (const float*)d_in[1];
    const float* bias   = (const float*)d_in[2];
    const float* unif   = (const float*)d_in[3];
    const float* uacc   = (const float*)d_in[4];
    const int*   radius = (const int*)d_in[5];
    float* out = (float*)d_out;

    static int smem_set = 0;
    if (!smem_set) {
        cudaFuncSetAttribute(gemm_mma, cudaFuncAttributeMaxDynamicSharedMemorySize, SMEM_TOTAL);
        smem_set = 1;
    }

    split_w_kernel<<<(DIM * DIM / 4) / 256, 256>>>(W);     // W -> 3x bf16 (exact)
    conv_x_kernel<<<(BSZ * DIM / 4) / 256, 256>>>(x);      // x -> bf16 (exact)
    gemm_mma<<<dim3(DIM / BN, BSZ / BM), 256, SMEM_TOTAL>>>(bias);  // grad_x (HMMA)
    scan_kernel<<<BSZ, 256>>>(x, unif, radius, bias);
    bwd_fused<<<BSZ, 256>>>(x, W, bias, uacc, radius, out);
}